// round 16
// baseline (speedup 1.0000x reference)
#include <cuda_runtime.h>
#include <cuda_fp16.h>
#include <cstdint>
#include <math.h>

// Problem constants
#define BB 2
#define SS 2048
#define DD 768
#define NH 12
#define DK 64
#define DV 64
#define GG 1
#define NIDX 6
#define SMID (SS - 2*GG)
#define MROWS (BB * SS)

// GEMM tiling
#define BM 128
#define BKK 32
#define NCHK (DD / BKK)
#define LDT 40

// Fused attention kernel geometry: global blocks FIRST, then persistent mid.
#define N_ITEMS (BB * NH * SMID)                  // 49104 (divisible by 4)
#define NBLK_MID 444                              // 148 SMs x 3 CTAs
#define NBLK_GLB (BB * NH * 2)                    // 48
#define MID_STRIDE (NBLK_MID * 8 * 4)             // items per loop round = 14208

// ---------------------------------------------------------------------------
// Scratch
// ---------------------------------------------------------------------------
__device__ float g_vsum[BB * DD];

__device__ __half g_qp[MROWS * DD];
__device__ __half g_kp[MROWS * DD];
__device__ __half g_vp[MROWS * DD];
__device__ __half g_qh[MROWS * DD];
__device__ __half g_kh[MROWS * DD];
__device__ __half g_vh[MROWS * DD];
__device__ __half g_ah[MROWS * DD], g_al[MROWS * DD];
__device__ __half g_wqh[DD * DD];
__device__ __half g_wkh[DD * DD];
__device__ __half g_wvh[DD * DD], g_wvl[DD * DD];
__device__ __half g_woh[DD * DD], g_wol[DD * DD];

// ---------------------------------------------------------------------------
// PTX helpers (portable sm_80+ ISA)
// ---------------------------------------------------------------------------
__device__ __forceinline__ uint32_t smem_u32(const void* p) {
    uint32_t a;
    asm("{ .reg .u64 t; cvta.to.shared.u64 t, %1; cvt.u32.u64 %0, t; }"
        : "=r"(a) : "l"(p));
    return a;
}
__device__ __forceinline__ void cp_async16(uint32_t dst, const void* src) {
    asm volatile("cp.async.cg.shared.global [%0], [%1], 16;"
                 :: "r"(dst), "l"(src) : "memory");
}
__device__ __forceinline__ void cp_commit() {
    asm volatile("cp.async.commit_group;" ::: "memory");
}
template <int N>
__device__ __forceinline__ void cp_wait() {
    asm volatile("cp.async.wait_group %0;" :: "n"(N) : "memory");
}
__device__ __forceinline__ void ldm4(uint32_t* r, uint32_t addr) {
    asm volatile("ldmatrix.sync.aligned.m8n8.x4.shared.b16 {%0,%1,%2,%3}, [%4];"
                 : "=r"(r[0]), "=r"(r[1]), "=r"(r[2]), "=r"(r[3]) : "r"(addr));
}
__device__ __forceinline__ void mma16816(float* c, const uint32_t* a, const uint32_t* b) {
    asm volatile(
        "mma.sync.aligned.m16n8k16.row.col.f32.f16.f16.f32 "
        "{%0,%1,%2,%3}, {%4,%5,%6,%7}, {%8,%9}, {%0,%1,%2,%3};"
        : "+f"(c[0]), "+f"(c[1]), "+f"(c[2]), "+f"(c[3])
        : "r"(a[0]), "r"(a[1]), "r"(a[2]), "r"(a[3]), "r"(b[0]), "r"(b[1]));
}

struct GemmArgs {
    const __half *Ah, *Al, *Bh, *Bl;
    float* C;
    __half* Ch;
    float* vsum;
    int nprod;        // 1: Ah*Bh ; 2: + Ah*Bl ; 3: + Al*Bh
};
struct Gemm3 { GemmArgs g[3]; };

// ---------------------------------------------------------------------------
// GEMM. HASAL: stage includes an A-lo tile (needed only for nprod==3).
// NSTGP: cp.async pipeline depth (2 or 3).
// ---------------------------------------------------------------------------
template <int BNT, bool HASAL, int NSTGP>
__global__ __launch_bounds__(256, 2) void gemm_mma(Gemm3 ga)
{
    constexpr int WNT = BNT / 4;
    constexpr int NJ = WNT / 8;
    constexpr int TILEB_A = 128 * LDT * 2;
    constexpr int TILEB_B = BNT * LDT * 2;
    constexpr int NA = HASAL ? 2 : 1;
    constexpr int STAGEB = NA * TILEB_A + 2 * TILEB_B;
    constexpr int ARC = NA * 128 * 4;                    // A-region chunks
    constexpr int NCHUNK = (NA * 128 + 2 * BNT) * 4;
    constexpr int PER_THR = NCHUNK / 256;

    extern __shared__ char smem[];
    const GemmArgs& A = ga.g[blockIdx.z];
    const int nprod = A.nprod;
    const uint32_t sb = smem_u32(smem);
    const int tid = threadIdx.x;
    const int wid = tid >> 5;
    const int lane = tid & 31;
    const int bm = blockIdx.y * BM;
    const int bn = blockIdx.x * BNT;
    const int wm = (wid >> 2) * 64;
    const int wn = (wid & 3) * WNT;

    float acc[4][NJ][4];
    #pragma unroll
    for (int i = 0; i < 4; i++)
        #pragma unroll
        for (int j = 0; j < NJ; j++)
            #pragma unroll
            for (int e = 0; e < 4; e++) acc[i][j][e] = 0.0f;

    auto issue = [&](int kt) {
        const int st = kt % NSTGP;
        #pragma unroll
        for (int q8 = 0; q8 < PER_THR; q8++) {
            int q = tid + q8 * 256;
            if (q < ARC) {
                int t = HASAL ? (q >> 9) : 0;
                if (HASAL && t == 1 && nprod < 3) continue;
                int r = (q >> 2) & 127;
                int c = q & 3;
                const __half* src = ((HASAL && t) ? A.Al : A.Ah)
                                    + (size_t)(bm + r) * DD + kt * BKK + c * 8;
                uint32_t dst = sb + st * STAGEB + t * TILEB_A + r * (LDT * 2) + c * 16;
                cp_async16(dst, src);
            } else {
                int q2 = q - ARC;
                int t = q2 / (BNT * 4);
                if (t == 1 && nprod < 2) continue;
                int r = (q2 >> 2) % BNT;
                int c = q2 & 3;
                const __half* src = (t ? A.Bl : A.Bh)
                                    + (size_t)(bn + r) * DD + kt * BKK + c * 8;
                uint32_t dst = sb + st * STAGEB + NA * TILEB_A + t * TILEB_B
                             + r * (LDT * 2) + c * 16;
                cp_async16(dst, src);
            }
        }
        cp_commit();
    };

    const int a_row = lane & 15;
    const int a_col = (lane >> 4) * 8;
    const int b_row = (lane & 7) + ((lane >> 4) << 3);
    const int b_col = ((lane >> 3) & 1) * 8;

    auto compute = [&](int kt) {
        const uint32_t base = sb + (kt % NSTGP) * STAGEB;
        #pragma unroll
        for (int ks = 0; ks < 2; ks++) {
            const int k0 = ks * 16;
            uint32_t bh[NJ / 2][4], bl[NJ / 2][4];
            #pragma unroll
            for (int nh = 0; nh < NJ / 2; nh++) {
                uint32_t off = (uint32_t)(wn + nh * 16 + b_row) * (LDT * 2)
                             + (k0 + b_col) * 2;
                ldm4(bh[nh], base + NA * TILEB_A + off);
                if (nprod >= 2)
                    ldm4(bl[nh], base + NA * TILEB_A + TILEB_B + off);
            }
            uint32_t af[4][4];
            #pragma unroll
            for (int mt = 0; mt < 4; mt++) {
                uint32_t off = (uint32_t)(wm + mt * 16 + a_row) * (LDT * 2)
                             + (k0 + a_col) * 2;
                ldm4(af[mt], base + off);
            }
            #pragma unroll
            for (int mt = 0; mt < 4; mt++)
                #pragma unroll
                for (int j = 0; j < NJ; j++) {
                    mma16816(acc[mt][j], af[mt], &bh[j >> 1][(j & 1) * 2]);
                    if (nprod >= 2)
                        mma16816(acc[mt][j], af[mt], &bl[j >> 1][(j & 1) * 2]);
                }
            if (HASAL) {
                if (nprod >= 3) {
                    #pragma unroll
                    for (int mt = 0; mt < 4; mt++) {
                        uint32_t off = (uint32_t)(wm + mt * 16 + a_row) * (LDT * 2)
                                     + (k0 + a_col) * 2;
                        ldm4(af[mt], base + TILEB_A + off);
                    }
                    #pragma unroll
                    for (int mt = 0; mt < 4; mt++)
                        #pragma unroll
                        for (int j = 0; j < NJ; j++)
                            mma16816(acc[mt][j], af[mt], &bh[j >> 1][(j & 1) * 2]);
                }
            }
        }
    };

    if (NSTGP == 2) {
        issue(0);
        for (int kt = 0; kt < NCHK; kt++) {
            cp_wait<0>();
            __syncthreads();
            if (kt + 1 < NCHK) issue(kt + 1);
            compute(kt);
        }
    } else {
        issue(0);
        issue(1);
        for (int kt = 0; kt < NCHK; kt++) {
            if (kt + 1 < NCHK) cp_wait<1>();
            else               cp_wait<0>();
            __syncthreads();
            if (kt + 2 < NCHK) issue(kt + 2);   // overwrites stage (kt-1)%3 — safe
            compute(kt);
        }
    }

    if (A.Ch) {
        #pragma unroll
        for (int mt = 0; mt < 4; mt++) {
            #pragma unroll
            for (int j = 0; j < NJ; j++) {
                int row = bm + wm + mt * 16 + (lane >> 2);
                int col = bn + wn + j * 8 + (lane & 3) * 2;
                *reinterpret_cast<__half2*>(A.Ch + (size_t)row * DD + col)
                    = __floats2half2_rn(acc[mt][j][0], acc[mt][j][1]);
                *reinterpret_cast<__half2*>(A.Ch + (size_t)(row + 8) * DD + col)
                    = __floats2half2_rn(acc[mt][j][2], acc[mt][j][3]);
            }
        }
    } else {
        #pragma unroll
        for (int mt = 0; mt < 4; mt++) {
            #pragma unroll
            for (int j = 0; j < NJ; j++) {
                int row = bm + wm + mt * 16 + (lane >> 2);
                int col = bn + wn + j * 8 + (lane & 3) * 2;
                *reinterpret_cast<float2*>(A.C + (size_t)row * DD + col)
                    = make_float2(acc[mt][j][0], acc[mt][j][1]);
                *reinterpret_cast<float2*>(A.C + (size_t)(row + 8) * DD + col)
                    = make_float2(acc[mt][j][2], acc[mt][j][3]);
            }
        }
    }

    if (A.vsum) {
        int b = bm / SS;
        #pragma unroll
        for (int j = 0; j < NJ; j++) {
            float s0 = 0.0f, s1 = 0.0f;
            #pragma unroll
            for (int mt = 0; mt < 4; mt++) {
                s0 += acc[mt][j][0] + acc[mt][j][2];
                s1 += acc[mt][j][1] + acc[mt][j][3];
            }
            #pragma unroll
            for (int o = 4; o < 32; o <<= 1) {
                s0 += __shfl_xor_sync(0xFFFFFFFFu, s0, o);
                s1 += __shfl_xor_sync(0xFFFFFFFFu, s1, o);
            }
            if (lane < 4) {
                int col = bn + wn + j * 8 + lane * 2;
                atomicAdd(&A.vsum[b * DD + col], s0);
                atomicAdd(&A.vsum[b * DD + col + 1], s1);
            }
        }
    }
}

// ---------------------------------------------------------------------------
// fp32 -> (f16 hi, f16 lo) splits
// ---------------------------------------------------------------------------
__device__ __forceinline__ void split4h(float4 v, ushort4& h, ushort4& l) {
    __half b;
    b = __float2half(v.x); h.x = __half_as_ushort(b);
    l.x = __half_as_ushort(__float2half(v.x - __half2float(b)));
    b = __float2half(v.y); h.y = __half_as_ushort(b);
    l.y = __half_as_ushort(__float2half(v.y - __half2float(b)));
    b = __float2half(v.z); h.z = __half_as_ushort(b);
    l.z = __half_as_ushort(__float2half(v.z - __half2float(b)));
    b = __float2half(v.w); h.w = __half_as_ushort(b);
    l.w = __half_as_ushort(__float2half(v.w - __half2float(b)));
}

struct SplitN {
    const float4* x[4];
    ushort4* hi[4];
    ushort4* lo[4];
    int zero_vsum;
};
__global__ void split_multi(SplitN a, int n4)
{
    int w = blockIdx.y;
    int i = blockIdx.x * blockDim.x + threadIdx.x;
    if (a.zero_vsum && w == 0 && i < BB * DD) g_vsum[i] = 0.0f;
    if (i >= n4) return;
    ushort4 h, l;
    split4h(a.x[w][i], h, l);
    a.hi[w][i] = h;
    if (a.lo[w]) a.lo[w][i] = l;
}

// ---------------------------------------------------------------------------
// Fused attention. Blocks [0,NBLK_GLB): global rows (coalesced). Then
// NBLK_MID persistent mid blocks (8 lanes/item, 4 items/warp).
// ---------------------------------------------------------------------------
__device__ __forceinline__ void store_hl(size_t off, float v) {
    __half h = __float2half(v);
    g_ah[off] = h;
    g_al[off] = __float2half(v - __half2float(h));
}

__global__ __launch_bounds__(256, 3) void attn_kernel(const int* __restrict__ idx)
{
    if (blockIdx.x >= NBLK_GLB) {
        // ------------------- middle rows (persistent) -------------------
        int lane = threadIdx.x & 31;
        int grp = lane >> 3;
        int d = lane & 7;
        int gw = (blockIdx.x - NBLK_GLB) * 8 + (threadIdx.x >> 5);

        for (int base = gw * 4; base < N_ITEMS; base += MID_STRIDE) {
            int item = base + grp;

            int i = item % SMID;
            int h = (item / SMID) % NH;
            int b = item / (SMID * NH);
            int s = i + GG;

            const int2* ip = reinterpret_cast<const int2*>(idx + i * NIDX);
            int2 c0 = ip[0], c1 = ip[1], c2 = ip[2];
            int cols[NIDX] = {c0.x, c0.y, c1.x, c1.y, c2.x, c2.y};

            uint32_t rowq = ((unsigned)(b * SS + s) * DD + h * DK + d * 8) * 2;
            uint4 qv = *reinterpret_cast<const uint4*>(
                reinterpret_cast<const char*>(g_qp) + rowq);
            const __half2* q2 = reinterpret_cast<const __half2*>(&qv);

            uint4 kv[NIDX], vv[NIDX];
            #pragma unroll
            for (int j = 0; j < NIDX; j++) {
                uint32_t ro = ((unsigned)(b * SS + cols[j]) * DD + h * DK + d * 8) * 2;
                kv[j] = *reinterpret_cast<const uint4*>(
                    reinterpret_cast<const char*>(g_kp) + ro);
                vv[j] = *reinterpret_cast<const uint4*>(
                    reinterpret_cast<const char*>(g_vp) + ro);
            }

            float sc[NIDX];
            #pragma unroll
            for (int j = 0; j < NIDX; j++) {
                const __half2* k2 = reinterpret_cast<const __half2*>(&kv[j]);
                __half2 a2 = __hmul2(q2[0], k2[0]);
                a2 = __hfma2(q2[1], k2[1], a2);
                a2 = __hfma2(q2[2], k2[2], a2);
                a2 = __hfma2(q2[3], k2[3], a2);
                float2 pf = __half22float2(a2);
                float p = pf.x + pf.y;
                p += __shfl_xor_sync(0xFFFFFFFFu, p, 1);
                p += __shfl_xor_sync(0xFFFFFFFFu, p, 2);
                p += __shfl_xor_sync(0xFFFFFFFFu, p, 4);
                sc[j] = p;
            }

            float denom = (float)SS;
            __half2 w2[NIDX];
            #pragma unroll
            for (int j = 0; j < NIDX; j++) {
                bool dup = (j > 0) && (cols[j] == cols[0]);
                float wv = dup ? 0.0f : (__expf(sc[j] * 0.125f) - 1.0f);
                denom += wv;
                w2[j] = __half2half2(__float2half_rn(wv));
            }

            __half2 corr[4];
            {
                const __half2* v2 = reinterpret_cast<const __half2*>(&vv[0]);
                #pragma unroll
                for (int e = 0; e < 4; e++) corr[e] = __hmul2(w2[0], v2[e]);
            }
            #pragma unroll
            for (int j = 1; j < NIDX; j++) {
                const __half2* v2 = reinterpret_cast<const __half2*>(&vv[j]);
                #pragma unroll
                for (int e = 0; e < 4; e++) corr[e] = __hfma2(w2[j], v2[e], corr[e]);
            }

            const float* vs = g_vsum + b * DD + h * DV + d * 8;
            float4 u0 = *reinterpret_cast<const float4*>(vs);
            float4 u1 = *reinterpret_cast<const float4*>(vs + 4);
            float inv = 1.0f / denom;
            float2 cf0 = __half22float2(corr[0]);
            float2 cf1 = __half22float2(corr[1]);
            float2 cf2 = __half22float2(corr[2]);
            float2 cf3 = __half22float2(corr[3]);
            float of[8] = {(u0.x + cf0.x) * inv, (u0.y + cf0.y) * inv,
                           (u0.z + cf1.x) * inv, (u0.w + cf1.y) * inv,
                           (u1.x + cf2.x) * inv, (u1.y + cf2.y) * inv,
                           (u1.z + cf3.x) * inv, (u1.w + cf3.y) * inv};

            __half2 hi[4], lo[4];
            #pragma unroll
            for (int e = 0; e < 4; e++) {
                __half h0 = __float2half(of[2 * e]);
                __half h1 = __float2half(of[2 * e + 1]);
                hi[e] = __halves2half2(h0, h1);
                lo[e] = __halves2half2(
                    __float2half(of[2 * e] - __half2float(h0)),
                    __float2half(of[2 * e + 1] - __half2float(h1)));
            }
            size_t obase = ((size_t)b * SS + s) * DD + h * DV + d * 8;
            *reinterpret_cast<uint4*>(g_ah + obase) = *reinterpret_cast<uint4*>(hi);
            *reinterpret_cast<uint4*>(g_al + obase) = *reinterpret_cast<uint4*>(lo);
        }
    } else {
        // ------------------- global rows (coalesced) -------------------
        int item = blockIdx.x;
        int r = item % 2;
        int h = (item / 2) % NH;
        int b = item / (2 * NH);
        int s = r ? (SS - 1) : 0;
        int tid = threadIdx.x;
        int warp = tid >> 5;
        int lane = tid & 31;
        int grp = lane >> 3;
        int d = lane & 7;

        __shared__ float sc[SS];
        __shared__ float red[256];

        uint32_t rowq = ((unsigned)(b * SS + s) * DD + h * DK + d * 8) * 2;
        uint4 qv = *reinterpret_cast<const uint4*>(
            reinterpret_cast<const char*>(g_qp) + rowq);
        const __half2* q2 = reinterpret_cast<const __half2*>(&qv);

        const char* kbase = reinterpret_cast<const char*>(g_kp)
                          + ((unsigned)(b * SS) * DD + h * DK + d * 8) * 2;
        for (int t = warp * 4 + grp; t < SS; t += 32) {
            uint4 kvv = *reinterpret_cast<const uint4*>(kbase + (unsigned)t * (DD * 2));
            const __half2* k2 = reinterpret_cast<const __half2*>(&kvv);
            __half2 a2 = __hmul2(q2[0], k2[0]);
            a2 = __hfma2(q2[1], k2[1], a2);
            a2 = __hfma2(q2[2], k2[2], a2);
            a2 = __hfma2(q2[3], k2[3], a2);
            float2 pf = __half22float2(a2);
            float p = pf.x + pf.y;
            p += __shfl_xor_sync(0xFFFFFFFFu, p, 1);
            p += __shfl_xor_sync(0xFFFFFFFFu, p, 2);
            p += __shfl_xor_sync(0xFFFFFFFFu, p, 4);
            if (d == 0) sc[t] = p * 0.125f;
        }
        __syncthreads();

        float m = -1e30f;
        for (int t = tid; t < SS; t += 256) m = fmaxf(m, sc[t]);
        red[tid] = m; __syncthreads();
        for (int o = 128; o > 0; o >>= 1) {
            if (tid < o) red[tid] = fmaxf(red[tid], red[tid + o]);
            __syncthreads();
        }
        m = red[0];
        __syncthreads();

        float sum = 0.0f;
        for (int t = tid; t < SS; t += 256) {
            float e = __expf(sc[t] - m);
            sc[t] = e;
            sum += e;
        }
        red[tid] = sum; __syncthreads();
        for (int o = 128; o > 0; o >>= 1) {
            if (tid < o) red[tid] += red[tid + o];
            __syncthreads();
        }
        float inv = 1.0f / red[0];
        __syncthreads();

        int dv = tid % DV;
        int chunk = tid / DV;
        float acc = 0.0f;
        const __half* vb = g_vp + (size_t)b * SS * DD + h * DV + dv;
        for (int t = chunk * (SS / 4); t < (chunk + 1) * (SS / 4); t++)
            acc = fmaf(sc[t], __half2float(vb[(size_t)t * DD]), acc);
        red[tid] = acc; __syncthreads();
        if (tid < DV) {
            float o = (red[dv] + red[DV + dv] + red[2 * DV + dv] + red[3 * DV + dv]) * inv;
            store_hl(((size_t)b * SS + s) * DD + h * DV + dv, o);
        }
    }
}

// ---------------------------------------------------------------------------
extern "C" void kernel_launch(void* const* d_in, const int* in_sizes, int n_in,
                              void* d_out, int out_size)
{
    const float* Q  = (const float*)d_in[0];
    const float* K  = (const float*)d_in[1];
    const float* V  = (const float*)d_in[2];
    const float* Wq = (const float*)d_in[3];
    const float* Wk = (const float*)d_in[4];
    const float* Wv = (const float*)d_in[5];
    const float* Wo = (const float*)d_in[6];
    const int*   idx = (const int*)d_in[7];
    float* out = (float*)d_out;

    float* pvs;
    cudaGetSymbolAddress((void**)&pvs, g_vsum);

    __half *qp, *kp, *vp, *qh, *kh, *vh, *ah, *al;
    __half *wqh, *wkh, *wvh, *wvl, *woh, *wol;
    cudaGetSymbolAddress((void**)&qp, g_qp);
    cudaGetSymbolAddress((void**)&kp, g_kp);
    cudaGetSymbolAddress((void**)&vp, g_vp);
    cudaGetSymbolAddress((void**)&qh, g_qh);
    cudaGetSymbolAddress((void**)&kh, g_kh);
    cudaGetSymbolAddress((void**)&vh, g_vh);
    cudaGetSymbolAddress((void**)&ah, g_ah);  cudaGetSymbolAddress((void**)&al, g_al);
    cudaGetSymbolAddress((void**)&wqh, g_wqh);
    cudaGetSymbolAddress((void**)&wkh, g_wkh);
    cudaGetSymbolAddress((void**)&wvh, g_wvh); cudaGetSymbolAddress((void**)&wvl, g_wvl);
    cudaGetSymbolAddress((void**)&woh, g_woh); cudaGetSymbolAddress((void**)&wol, g_wol);

    // QKV: no A-lo tile, 3-stage pipeline. O: A-lo tile, 2-stage.
    constexpr int SMEM_QKV = 3 * (1 * 128 * LDT * 2 + 2 * 128 * LDT * 2);  // 92160
    constexpr int SMEM_O   = 2 * (2 * 128 * LDT * 2 + 2 * 128 * LDT * 2);  // 81920
    cudaFuncSetAttribute((const void*)gemm_mma<128, false, 3>,
                         cudaFuncAttributeMaxDynamicSharedMemorySize, SMEM_QKV);
    cudaFuncSetAttribute((const void*)gemm_mma<128, true, 2>,
                         cudaFuncAttributeMaxDynamicSharedMemorySize, SMEM_O);

    const int n4_big = MROWS * DD / 4;
    const int n4_w   = DD * DD / 4;
    const int bl_big = (n4_big + 255) / 256;
    const int bl_w   = (n4_w + 255) / 256;

    SplitN si;
    si.x[0] = (const float4*)Q; si.hi[0] = (ushort4*)qh; si.lo[0] = nullptr;
    si.x[1] = (const float4*)K; si.hi[1] = (ushort4*)kh; si.lo[1] = nullptr;
    si.x[2] = (const float4*)V; si.hi[2] = (ushort4*)vh; si.lo[2] = nullptr;
    si.x[3] = si.x[0]; si.hi[3] = si.hi[0]; si.lo[3] = nullptr;
    si.zero_vsum = 0;
    split_multi<<<dim3(bl_big, 3), 256>>>(si, n4_big);

    SplitN sw;
    sw.x[0] = (const float4*)Wq; sw.hi[0] = (ushort4*)wqh; sw.lo[0] = nullptr;
    sw.x[1] = (const float4*)Wk; sw.hi[1] = (ushort4*)wkh; sw.lo[1] = nullptr;
    sw.x[2] = (const float4*)Wv; sw.hi[2] = (ushort4*)wvh; sw.lo[2] = (ushort4*)wvl;
    sw.x[3] = (const float4*)Wo; sw.hi[3] = (ushort4*)woh; sw.lo[3] = (ushort4*)wol;
    sw.zero_vsum = 1;
    split_multi<<<dim3(bl_w, 4), 256>>>(sw, n4_w);

    Gemm3 g3;
    g3.g[0] = {vh, nullptr, wvh, wvl, nullptr, vp, pvs, 2};
    g3.g[1] = {qh, nullptr, wqh, nullptr, nullptr, qp, nullptr, 1};
    g3.g[2] = {kh, nullptr, wkh, nullptr, nullptr, kp, nullptr, 1};
    gemm_mma<128, false, 3><<<dim3(DD / 128, MROWS / BM, 3), 256, SMEM_QKV>>>(g3);

    attn_kernel<<<NBLK_GLB + NBLK_MID, 256>>>(idx);

    Gemm3 go;
    go.g[0] = {ah, al, woh, wol, out, nullptr, nullptr, 3};
    go.g[1] = go.g[0];
    go.g[2] = go.g[0];
    gemm_mma<128, true, 2><<<dim3(DD / 128, MROWS / BM, 1), 256, SMEM_O>>>(go);
}

// round 17
// speedup vs baseline: 1.2796x; 1.2796x over previous
#include <cuda_runtime.h>
#include <cuda_fp16.h>
#include <cstdint>
#include <math.h>

// Problem constants
#define BB 2
#define SS 2048
#define DD 768
#define NH 12
#define DK 64
#define DV 64
#define GG 1
#define NIDX 6
#define SMID (SS - 2*GG)
#define MROWS (BB * SS)

// GEMM tiling
#define BM 128
#define BKK 32
#define NCHK (DD / BKK)
#define LDT 40
#define NSTG 2

// Fused attention kernel geometry: global blocks FIRST, then persistent mid.
#define N_ITEMS (BB * NH * SMID)                  // 49104 (divisible by 4)
#define NBLK_MID 444                              // 148 SMs x 3 CTAs
#define NBLK_GLB (BB * NH * 2)                    // 48
#define MID_STRIDE (NBLK_MID * 8 * 4)             // items per loop round = 14208

// ---------------------------------------------------------------------------
// Scratch
// ---------------------------------------------------------------------------
__device__ float g_vsum[BB * DD];

__device__ __half g_qp[MROWS * DD];
__device__ __half g_kp[MROWS * DD];
__device__ __half g_vp[MROWS * DD];
__device__ __half g_qh[MROWS * DD];
__device__ __half g_kh[MROWS * DD];
__device__ __half g_vh[MROWS * DD];
__device__ __half g_ah[MROWS * DD];
__device__ __half g_wqh[DD * DD];
__device__ __half g_wkh[DD * DD];
__device__ __half g_wvh[DD * DD], g_wvl[DD * DD];
__device__ __half g_woh[DD * DD], g_wol[DD * DD];

// ---------------------------------------------------------------------------
// PTX helpers (portable sm_80+ ISA)
// ---------------------------------------------------------------------------
__device__ __forceinline__ uint32_t smem_u32(const void* p) {
    uint32_t a;
    asm("{ .reg .u64 t; cvta.to.shared.u64 t, %1; cvt.u32.u64 %0, t; }"
        : "=r"(a) : "l"(p));
    return a;
}
__device__ __forceinline__ void cp_async16(uint32_t dst, const void* src) {
    asm volatile("cp.async.cg.shared.global [%0], [%1], 16;"
                 :: "r"(dst), "l"(src) : "memory");
}
__device__ __forceinline__ void cp_commit() {
    asm volatile("cp.async.commit_group;" ::: "memory");
}
template <int N>
__device__ __forceinline__ void cp_wait() {
    asm volatile("cp.async.wait_group %0;" :: "n"(N) : "memory");
}
__device__ __forceinline__ void ldm4(uint32_t* r, uint32_t addr) {
    asm volatile("ldmatrix.sync.aligned.m8n8.x4.shared.b16 {%0,%1,%2,%3}, [%4];"
                 : "=r"(r[0]), "=r"(r[1]), "=r"(r[2]), "=r"(r[3]) : "r"(addr));
}
__device__ __forceinline__ void mma16816(float* c, const uint32_t* a, const uint32_t* b) {
    asm volatile(
        "mma.sync.aligned.m16n8k16.row.col.f32.f16.f16.f32 "
        "{%0,%1,%2,%3}, {%4,%5,%6,%7}, {%8,%9}, {%0,%1,%2,%3};"
        : "+f"(c[0]), "+f"(c[1]), "+f"(c[2]), "+f"(c[3])
        : "r"(a[0]), "r"(a[1]), "r"(a[2]), "r"(a[3]), "r"(b[0]), "r"(b[1]));
}

struct GemmArgs {
    const __half *Ah, *Bh, *Bl;
    float* C;
    __half* Ch;
    float* vsum;
    int nprod;        // 1: Ah*Bh ; 2: + Ah*Bl
};
struct Gemm3 { GemmArgs g[3]; };

// ---------------------------------------------------------------------------
// GEMM: C = Ah*Bh^T (+ Ah*Bl^T). 128x128 tile, NSTG=2, 2 CTAs/SM. No A-lo.
// ---------------------------------------------------------------------------
template <int BNT>
__global__ __launch_bounds__(256, 2) void gemm_mma(Gemm3 ga)
{
    constexpr int WNT = BNT / 4;
    constexpr int NJ = WNT / 8;
    constexpr int TILEB_A = 128 * LDT * 2;
    constexpr int TILEB_B = BNT * LDT * 2;
    constexpr int STAGEB = TILEB_A + 2 * TILEB_B;           // 30720
    constexpr int ARC = 128 * 4;                            // A chunks
    constexpr int NCHUNK = (128 + 2 * BNT) * 4;
    constexpr int PER_THR = NCHUNK / 256;

    extern __shared__ char smem[];
    const GemmArgs& A = ga.g[blockIdx.z];
    const int nprod = A.nprod;
    const uint32_t sb = smem_u32(smem);
    const int tid = threadIdx.x;
    const int wid = tid >> 5;
    const int lane = tid & 31;
    const int bm = blockIdx.y * BM;
    const int bn = blockIdx.x * BNT;
    const int wm = (wid >> 2) * 64;
    const int wn = (wid & 3) * WNT;

    float acc[4][NJ][4];
    #pragma unroll
    for (int i = 0; i < 4; i++)
        #pragma unroll
        for (int j = 0; j < NJ; j++)
            #pragma unroll
            for (int e = 0; e < 4; e++) acc[i][j][e] = 0.0f;

    auto issue = [&](int kt) {
        const int st = kt % NSTG;
        #pragma unroll
        for (int q8 = 0; q8 < PER_THR; q8++) {
            int q = tid + q8 * 256;
            if (q < ARC) {
                int r = (q >> 2) & 127;
                int c = q & 3;
                const __half* src = A.Ah + (size_t)(bm + r) * DD + kt * BKK + c * 8;
                uint32_t dst = sb + st * STAGEB + r * (LDT * 2) + c * 16;
                cp_async16(dst, src);
            } else {
                int q2 = q - ARC;
                int t = q2 / (BNT * 4);
                if (t == 1 && nprod < 2) continue;
                int r = (q2 >> 2) % BNT;
                int c = q2 & 3;
                const __half* src = (t ? A.Bl : A.Bh)
                                    + (size_t)(bn + r) * DD + kt * BKK + c * 8;
                uint32_t dst = sb + st * STAGEB + TILEB_A + t * TILEB_B
                             + r * (LDT * 2) + c * 16;
                cp_async16(dst, src);
            }
        }
        cp_commit();
    };

    const int a_row = lane & 15;
    const int a_col = (lane >> 4) * 8;
    const int b_row = (lane & 7) + ((lane >> 4) << 3);
    const int b_col = ((lane >> 3) & 1) * 8;

    auto compute = [&](int kt) {
        const uint32_t base = sb + (kt % NSTG) * STAGEB;
        #pragma unroll
        for (int ks = 0; ks < 2; ks++) {
            const int k0 = ks * 16;
            uint32_t bh[NJ / 2][4], bl[NJ / 2][4];
            #pragma unroll
            for (int nh = 0; nh < NJ / 2; nh++) {
                uint32_t off = (uint32_t)(wn + nh * 16 + b_row) * (LDT * 2)
                             + (k0 + b_col) * 2;
                ldm4(bh[nh], base + TILEB_A + off);
                if (nprod >= 2)
                    ldm4(bl[nh], base + TILEB_A + TILEB_B + off);
            }
            uint32_t af[4][4];
            #pragma unroll
            for (int mt = 0; mt < 4; mt++) {
                uint32_t off = (uint32_t)(wm + mt * 16 + a_row) * (LDT * 2)
                             + (k0 + a_col) * 2;
                ldm4(af[mt], base + off);
            }
            #pragma unroll
            for (int mt = 0; mt < 4; mt++)
                #pragma unroll
                for (int j = 0; j < NJ; j++) {
                    mma16816(acc[mt][j], af[mt], &bh[j >> 1][(j & 1) * 2]);
                    if (nprod >= 2)
                        mma16816(acc[mt][j], af[mt], &bl[j >> 1][(j & 1) * 2]);
                }
        }
    };

    issue(0);
    for (int kt = 0; kt < NCHK; kt++) {
        cp_wait<0>();
        __syncthreads();
        if (kt + 1 < NCHK) issue(kt + 1);
        compute(kt);
    }

    if (A.Ch) {
        #pragma unroll
        for (int mt = 0; mt < 4; mt++) {
            #pragma unroll
            for (int j = 0; j < NJ; j++) {
                int row = bm + wm + mt * 16 + (lane >> 2);
                int col = bn + wn + j * 8 + (lane & 3) * 2;
                *reinterpret_cast<__half2*>(A.Ch + (size_t)row * DD + col)
                    = __floats2half2_rn(acc[mt][j][0], acc[mt][j][1]);
                *reinterpret_cast<__half2*>(A.Ch + (size_t)(row + 8) * DD + col)
                    = __floats2half2_rn(acc[mt][j][2], acc[mt][j][3]);
            }
        }
    } else {
        #pragma unroll
        for (int mt = 0; mt < 4; mt++) {
            #pragma unroll
            for (int j = 0; j < NJ; j++) {
                int row = bm + wm + mt * 16 + (lane >> 2);
                int col = bn + wn + j * 8 + (lane & 3) * 2;
                *reinterpret_cast<float2*>(A.C + (size_t)row * DD + col)
                    = make_float2(acc[mt][j][0], acc[mt][j][1]);
                *reinterpret_cast<float2*>(A.C + (size_t)(row + 8) * DD + col)
                    = make_float2(acc[mt][j][2], acc[mt][j][3]);
            }
        }
    }

    if (A.vsum) {
        int b = bm / SS;
        #pragma unroll
        for (int j = 0; j < NJ; j++) {
            float s0 = 0.0f, s1 = 0.0f;
            #pragma unroll
            for (int mt = 0; mt < 4; mt++) {
                s0 += acc[mt][j][0] + acc[mt][j][2];
                s1 += acc[mt][j][1] + acc[mt][j][3];
            }
            #pragma unroll
            for (int o = 4; o < 32; o <<= 1) {
                s0 += __shfl_xor_sync(0xFFFFFFFFu, s0, o);
                s1 += __shfl_xor_sync(0xFFFFFFFFu, s1, o);
            }
            if (lane < 4) {
                int col = bn + wn + j * 8 + lane * 2;
                atomicAdd(&A.vsum[b * DD + col], s0);
                atomicAdd(&A.vsum[b * DD + col + 1], s1);
            }
        }
    }
}

// ---------------------------------------------------------------------------
// Single fused split kernel: 7 slices (Q,K,V inputs + 4 weights), flat grid.
// ---------------------------------------------------------------------------
__device__ __forceinline__ void split4h(float4 v, ushort4& h, ushort4& l) {
    __half b;
    b = __float2half(v.x); h.x = __half_as_ushort(b);
    l.x = __half_as_ushort(__float2half(v.x - __half2float(b)));
    b = __float2half(v.y); h.y = __half_as_ushort(b);
    l.y = __half_as_ushort(__float2half(v.y - __half2float(b)));
    b = __float2half(v.z); h.z = __half_as_ushort(b);
    l.z = __half_as_ushort(__float2half(v.z - __half2float(b)));
    b = __float2half(v.w); h.w = __half_as_ushort(b);
    l.w = __half_as_ushort(__float2half(v.w - __half2float(b)));
}

struct SplitAll {
    const float4* x[7];
    ushort4* hi[7];
    ushort4* lo[7];
    int blk0[8];      // block-range starts per slice; blk0[7] = total
    int n4[7];
};
__global__ void split_all(SplitAll a)
{
    int blk = blockIdx.x;
    if (blk < 6) {                      // fold vsum zeroing into first blocks
        int z = blk * 256 + threadIdx.x;
        if (z < BB * DD) g_vsum[z] = 0.0f;
    }
    int s = 0;
    #pragma unroll
    for (int t = 1; t < 7; t++)
        if (blk >= a.blk0[t]) s = t;
    int i = (blk - a.blk0[s]) * 256 + threadIdx.x;
    if (i >= a.n4[s]) return;
    ushort4 h, l;
    split4h(a.x[s][i], h, l);
    a.hi[s][i] = h;
    if (a.lo[s]) a.lo[s][i] = l;
}

// ---------------------------------------------------------------------------
// Fused attention. Blocks [0,NBLK_GLB): global rows (coalesced). Then
// NBLK_MID persistent mid blocks (8 lanes/item, 4 items/warp). hi-only out.
// ---------------------------------------------------------------------------
__global__ __launch_bounds__(256, 3) void attn_kernel(const int* __restrict__ idx)
{
    if (blockIdx.x >= NBLK_GLB) {
        // ------------------- middle rows (persistent) -------------------
        int lane = threadIdx.x & 31;
        int grp = lane >> 3;
        int d = lane & 7;
        int gw = (blockIdx.x - NBLK_GLB) * 8 + (threadIdx.x >> 5);

        for (int base = gw * 4; base < N_ITEMS; base += MID_STRIDE) {
            int item = base + grp;

            int i = item % SMID;
            int h = (item / SMID) % NH;
            int b = item / (SMID * NH);
            int s = i + GG;

            const int2* ip = reinterpret_cast<const int2*>(idx + i * NIDX);
            int2 c0 = ip[0], c1 = ip[1], c2 = ip[2];
            int cols[NIDX] = {c0.x, c0.y, c1.x, c1.y, c2.x, c2.y};

            uint32_t rowq = ((unsigned)(b * SS + s) * DD + h * DK + d * 8) * 2;
            uint4 qv = *reinterpret_cast<const uint4*>(
                reinterpret_cast<const char*>(g_qp) + rowq);
            const __half2* q2 = reinterpret_cast<const __half2*>(&qv);

            uint4 kv[NIDX], vv[NIDX];
            #pragma unroll
            for (int j = 0; j < NIDX; j++) {
                uint32_t ro = ((unsigned)(b * SS + cols[j]) * DD + h * DK + d * 8) * 2;
                kv[j] = *reinterpret_cast<const uint4*>(
                    reinterpret_cast<const char*>(g_kp) + ro);
                vv[j] = *reinterpret_cast<const uint4*>(
                    reinterpret_cast<const char*>(g_vp) + ro);
            }

            float sc[NIDX];
            #pragma unroll
            for (int j = 0; j < NIDX; j++) {
                const __half2* k2 = reinterpret_cast<const __half2*>(&kv[j]);
                __half2 a2 = __hmul2(q2[0], k2[0]);
                a2 = __hfma2(q2[1], k2[1], a2);
                a2 = __hfma2(q2[2], k2[2], a2);
                a2 = __hfma2(q2[3], k2[3], a2);
                float2 pf = __half22float2(a2);
                float p = pf.x + pf.y;
                p += __shfl_xor_sync(0xFFFFFFFFu, p, 1);
                p += __shfl_xor_sync(0xFFFFFFFFu, p, 2);
                p += __shfl_xor_sync(0xFFFFFFFFu, p, 4);
                sc[j] = p;
            }

            float denom = (float)SS;
            __half2 w2[NIDX];
            #pragma unroll
            for (int j = 0; j < NIDX; j++) {
                bool dup = (j > 0) && (cols[j] == cols[0]);
                float wv = dup ? 0.0f : (__expf(sc[j] * 0.125f) - 1.0f);
                denom += wv;
                w2[j] = __half2half2(__float2half_rn(wv));
            }

            __half2 corr[4];
            {
                const __half2* v2 = reinterpret_cast<const __half2*>(&vv[0]);
                #pragma unroll
                for (int e = 0; e < 4; e++) corr[e] = __hmul2(w2[0], v2[e]);
            }
            #pragma unroll
            for (int j = 1; j < NIDX; j++) {
                const __half2* v2 = reinterpret_cast<const __half2*>(&vv[j]);
                #pragma unroll
                for (int e = 0; e < 4; e++) corr[e] = __hfma2(w2[j], v2[e], corr[e]);
            }

            const float* vs = g_vsum + b * DD + h * DV + d * 8;
            float4 u0 = *reinterpret_cast<const float4*>(vs);
            float4 u1 = *reinterpret_cast<const float4*>(vs + 4);
            float inv = 1.0f / denom;
            float2 cf0 = __half22float2(corr[0]);
            float2 cf1 = __half22float2(corr[1]);
            float2 cf2 = __half22float2(corr[2]);
            float2 cf3 = __half22float2(corr[3]);

            __half2 hi[4];
            hi[0] = __floats2half2_rn((u0.x + cf0.x) * inv, (u0.y + cf0.y) * inv);
            hi[1] = __floats2half2_rn((u0.z + cf1.x) * inv, (u0.w + cf1.y) * inv);
            hi[2] = __floats2half2_rn((u1.x + cf2.x) * inv, (u1.y + cf2.y) * inv);
            hi[3] = __floats2half2_rn((u1.z + cf3.x) * inv, (u1.w + cf3.y) * inv);
            size_t obase = ((size_t)b * SS + s) * DD + h * DV + d * 8;
            *reinterpret_cast<uint4*>(g_ah + obase) = *reinterpret_cast<uint4*>(hi);
        }
    } else {
        // ------------------- global rows (coalesced) -------------------
        int item = blockIdx.x;
        int r = item % 2;
        int h = (item / 2) % NH;
        int b = item / (2 * NH);
        int s = r ? (SS - 1) : 0;
        int tid = threadIdx.x;
        int warp = tid >> 5;
        int lane = tid & 31;
        int grp = lane >> 3;
        int d = lane & 7;

        __shared__ float sc[SS];
        __shared__ float red[256];

        uint32_t rowq = ((unsigned)(b * SS + s) * DD + h * DK + d * 8) * 2;
        uint4 qv = *reinterpret_cast<const uint4*>(
            reinterpret_cast<const char*>(g_qp) + rowq);
        const __half2* q2 = reinterpret_cast<const __half2*>(&qv);

        const char* kbase = reinterpret_cast<const char*>(g_kp)
                          + ((unsigned)(b * SS) * DD + h * DK + d * 8) * 2;
        for (int t = warp * 4 + grp; t < SS; t += 32) {
            uint4 kvv = *reinterpret_cast<const uint4*>(kbase + (unsigned)t * (DD * 2));
            const __half2* k2 = reinterpret_cast<const __half2*>(&kvv);
            __half2 a2 = __hmul2(q2[0], k2[0]);
            a2 = __hfma2(q2[1], k2[1], a2);
            a2 = __hfma2(q2[2], k2[2], a2);
            a2 = __hfma2(q2[3], k2[3], a2);
            float2 pf = __half22float2(a2);
            float p = pf.x + pf.y;
            p += __shfl_xor_sync(0xFFFFFFFFu, p, 1);
            p += __shfl_xor_sync(0xFFFFFFFFu, p, 2);
            p += __shfl_xor_sync(0xFFFFFFFFu, p, 4);
            if (d == 0) sc[t] = p * 0.125f;
        }
        __syncthreads();

        float m = -1e30f;
        for (int t = tid; t < SS; t += 256) m = fmaxf(m, sc[t]);
        red[tid] = m; __syncthreads();
        for (int o = 128; o > 0; o >>= 1) {
            if (tid < o) red[tid] = fmaxf(red[tid], red[tid + o]);
            __syncthreads();
        }
        m = red[0];
        __syncthreads();

        float sum = 0.0f;
        for (int t = tid; t < SS; t += 256) {
            float e = __expf(sc[t] - m);
            sc[t] = e;
            sum += e;
        }
        red[tid] = sum; __syncthreads();
        for (int o = 128; o > 0; o >>= 1) {
            if (tid < o) red[tid] += red[tid + o];
            __syncthreads();
        }
        float inv = 1.0f / red[0];
        __syncthreads();

        int dv = tid % DV;
        int chunk = tid / DV;
        float acc = 0.0f;
        const __half* vb = g_vp + (size_t)b * SS * DD + h * DV + dv;
        for (int t = chunk * (SS / 4); t < (chunk + 1) * (SS / 4); t++)
            acc = fmaf(sc[t], __half2float(vb[(size_t)t * DD]), acc);
        red[tid] = acc; __syncthreads();
        if (tid < DV) {
            float o = (red[dv] + red[DV + dv] + red[2 * DV + dv] + red[3 * DV + dv]) * inv;
            g_ah[((size_t)b * SS + s) * DD + h * DV + dv] = __float2half(o);
        }
    }
}

// ---------------------------------------------------------------------------
extern "C" void kernel_launch(void* const* d_in, const int* in_sizes, int n_in,
                              void* d_out, int out_size)
{
    const float* Q  = (const float*)d_in[0];
    const float* K  = (const float*)d_in[1];
    const float* V  = (const float*)d_in[2];
    const float* Wq = (const float*)d_in[3];
    const float* Wk = (const float*)d_in[4];
    const float* Wv = (const float*)d_in[5];
    const float* Wo = (const float*)d_in[6];
    const int*   idx = (const int*)d_in[7];
    float* out = (float*)d_out;

    float* pvs;
    cudaGetSymbolAddress((void**)&pvs, g_vsum);

    __half *qp, *kp, *vp, *qh, *kh, *vh, *ah;
    __half *wqh, *wkh, *wvh, *wvl, *woh, *wol;
    cudaGetSymbolAddress((void**)&qp, g_qp);
    cudaGetSymbolAddress((void**)&kp, g_kp);
    cudaGetSymbolAddress((void**)&vp, g_vp);
    cudaGetSymbolAddress((void**)&qh, g_qh);
    cudaGetSymbolAddress((void**)&kh, g_kh);
    cudaGetSymbolAddress((void**)&vh, g_vh);
    cudaGetSymbolAddress((void**)&ah, g_ah);
    cudaGetSymbolAddress((void**)&wqh, g_wqh);
    cudaGetSymbolAddress((void**)&wkh, g_wkh);
    cudaGetSymbolAddress((void**)&wvh, g_wvh); cudaGetSymbolAddress((void**)&wvl, g_wvl);
    cudaGetSymbolAddress((void**)&woh, g_woh); cudaGetSymbolAddress((void**)&wol, g_wol);

    constexpr int SMEMG = NSTG * (128 * LDT * 2 + 2 * 128 * LDT * 2);  // 61440
    cudaFuncSetAttribute((const void*)gemm_mma<128>,
                         cudaFuncAttributeMaxDynamicSharedMemorySize, SMEMG);

    const int n4_big = MROWS * DD / 4;    // 786432
    const int n4_w   = DD * DD / 4;       // 147456
    const int bl_big = n4_big / 256;      // 3072
    const int bl_w   = n4_w / 256;        // 576

    SplitAll sa;
    sa.x[0] = (const float4*)Q;  sa.hi[0] = (ushort4*)qh;  sa.lo[0] = nullptr;
    sa.x[1] = (const float4*)K;  sa.hi[1] = (ushort4*)kh;  sa.lo[1] = nullptr;
    sa.x[2] = (const float4*)V;  sa.hi[2] = (ushort4*)vh;  sa.lo[2] = nullptr;
    sa.x[3] = (const float4*)Wq; sa.hi[3] = (ushort4*)wqh; sa.lo[3] = nullptr;
    sa.x[4] = (const float4*)Wk; sa.hi[4] = (ushort4*)wkh; sa.lo[4] = nullptr;
    sa.x[5] = (const float4*)Wv; sa.hi[5] = (ushort4*)wvh; sa.lo[5] = (ushort4*)wvl;
    sa.x[6] = (const float4*)Wo; sa.hi[6] = (ushort4*)woh; sa.lo[6] = (ushort4*)wol;
    int blk = 0;
    for (int s = 0; s < 7; s++) {
        sa.blk0[s] = blk;
        sa.n4[s] = (s < 3) ? n4_big : n4_w;
        blk += (s < 3) ? bl_big : bl_w;
    }
    sa.blk0[7] = blk;                      // 11520 blocks
    split_all<<<blk, 256>>>(sa);

    Gemm3 g3;
    g3.g[0] = {vh, wvh, wvl, nullptr, vp, pvs, 2};
    g3.g[1] = {qh, wqh, nullptr, nullptr, qp, nullptr, 1};
    g3.g[2] = {kh, wkh, nullptr, nullptr, kp, nullptr, 1};
    gemm_mma<128><<<dim3(DD / 128, MROWS / BM, 3), 256, SMEMG>>>(g3);

    attn_kernel<<<NBLK_GLB + NBLK_MID, 256>>>(idx);

    Gemm3 go;
    go.g[0] = {ah, woh, wol, out, nullptr, nullptr, 2};
    go.g[1] = go.g[0];
    go.g[2] = go.g[0];
    gemm_mma<128><<<dim3(DD / 128, MROWS / BM, 1), 256, SMEMG>>>(go);
}